// round 3
// baseline (speedup 1.0000x reference)
#include <cuda_runtime.h>
#include <cuda_bf16.h>
#include <math.h>

// ---------------------------------------------------------------------------
// Problem constants
// ---------------------------------------------------------------------------
#define BATCH     2
#define SEQ       8192
#define HID       1024
#define NHEADS    16
#define HDIM      64
#define KWIN      7
#define ATT_SCALE 0.125f   // 1/sqrt(64)

#define M_ROWS (BATCH * SEQ)          // 16384

// Scratch (allowed: __device__ globals, no runtime allocation)
__device__ float g_q[(size_t)M_ROWS * HID];
__device__ float g_k[(size_t)M_ROWS * HID];
__device__ float g_v[(size_t)M_ROWS * HID];
__device__ float g_attn[(size_t)M_ROWS * HID];

// ---------------------------------------------------------------------------
// Packed f32x2 helpers (FFMA2 — not emitted by ptxas from C++)
// ---------------------------------------------------------------------------
__device__ __forceinline__ unsigned long long f2_dup(float x) {
    unsigned long long r;
    asm("mov.b64 %0, {%1, %1};" : "=l"(r) : "f"(x));
    return r;
}
__device__ __forceinline__ unsigned long long f2_pack(float x, float y) {
    unsigned long long r;
    asm("mov.b64 %0, {%1, %2};" : "=l"(r) : "f"(x), "f"(y));
    return r;
}
__device__ __forceinline__ unsigned long long f2_fma(unsigned long long a,
                                                     unsigned long long b,
                                                     unsigned long long c) {
    unsigned long long d;
    asm("fma.rn.f32x2 %0, %1, %2, %3;" : "=l"(d) : "l"(a), "l"(b), "l"(c));
    return d;
}
__device__ __forceinline__ float2 f2_unpack(unsigned long long p) {
    float2 v;
    asm("mov.b64 {%0, %1}, %2;" : "=f"(v.x), "=f"(v.y) : "l"(p));
    return v;
}

// ---------------------------------------------------------------------------
// GEMM: C[M,N] = A[M,K] @ B[K,N] + bias[N]
// A row-major, B row-major, C row-major. M%128==0, N%128==0, K%16==0.
// 128x128 tile, BK=16, 256 threads, 8x8 per-thread tile, packed-f32x2 FMAs.
// ---------------------------------------------------------------------------
#define BM 128
#define BN 128
#define BK 16
#define TM 8
#define TN 8

__global__ void __launch_bounds__(256, 2)
gemm_bias_kernel(const float* __restrict__ A, const float* __restrict__ B,
                 const float* __restrict__ bias, float* __restrict__ C,
                 int M, int N, int K)
{
    __shared__ float As[BK][BM];   // A tile, transposed (k-major rows)
    __shared__ float Bs[BK][BN];

    const int tid = threadIdx.x;
    const int tx  = tid & 15;      // 0..15 -> N
    const int ty  = tid >> 4;      // 0..15 -> M
    const int m0  = blockIdx.y * BM;
    const int n0  = blockIdx.x * BN;

    const float* Ab = A + (size_t)m0 * K;
    const float* Bb = B + n0;

    unsigned long long acc[TM][TN / 2];
#pragma unroll
    for (int i = 0; i < TM; i++)
#pragma unroll
        for (int j = 0; j < TN / 2; j++) acc[i][j] = 0ULL;

    for (int kt = 0; kt < K; kt += BK) {
        // --- load A tile 128x16 (transpose into As[k][m]) ---
#pragma unroll
        for (int r = 0; r < 2; r++) {
            int idx = tid + r * 256;           // 0..511 float4s
            int row = idx >> 2;                // 0..127
            int c4  = (idx & 3) << 2;          // 0,4,8,12
            float4 av = *(const float4*)(Ab + (size_t)row * K + kt + c4);
            As[c4 + 0][row] = av.x;
            As[c4 + 1][row] = av.y;
            As[c4 + 2][row] = av.z;
            As[c4 + 3][row] = av.w;
        }
        // --- load B tile 16x128 (direct) ---
#pragma unroll
        for (int r = 0; r < 2; r++) {
            int idx = tid + r * 256;
            int row = idx >> 5;                // 0..15
            int c4  = (idx & 31) << 2;         // 0..124
            *(float4*)&Bs[row][c4] =
                *(const float4*)(Bb + (size_t)(kt + row) * N + c4);
        }
        __syncthreads();

#pragma unroll
        for (int kk = 0; kk < BK; kk++) {
            float4 a0 = *(const float4*)&As[kk][ty * 8];
            float4 a4 = *(const float4*)&As[kk][ty * 8 + 4];
            float4 b0 = *(const float4*)&Bs[kk][tx * 8];
            float4 b4 = *(const float4*)&Bs[kk][tx * 8 + 4];

            unsigned long long bp[4];
            bp[0] = f2_pack(b0.x, b0.y);
            bp[1] = f2_pack(b0.z, b0.w);
            bp[2] = f2_pack(b4.x, b4.y);
            bp[3] = f2_pack(b4.z, b4.w);

            float av[TM] = {a0.x, a0.y, a0.z, a0.w, a4.x, a4.y, a4.z, a4.w};
#pragma unroll
            for (int i = 0; i < TM; i++) {
                unsigned long long ai = f2_dup(av[i]);
#pragma unroll
                for (int j = 0; j < TN / 2; j++)
                    acc[i][j] = f2_fma(ai, bp[j], acc[i][j]);
            }
        }
        __syncthreads();
    }

    // --- epilogue: unpack, add bias, store ---
    float bv[TN];
#pragma unroll
    for (int j = 0; j < TN; j++) bv[j] = bias[n0 + tx * 8 + j];

#pragma unroll
    for (int i = 0; i < TM; i++) {
        int row = m0 + ty * 8 + i;
        float out[TN];
#pragma unroll
        for (int j = 0; j < TN / 2; j++) {
            float2 v = f2_unpack(acc[i][j]);
            out[2 * j]     = v.x + bv[2 * j];
            out[2 * j + 1] = v.y + bv[2 * j + 1];
        }
        float* cp = C + (size_t)row * N + n0 + tx * 8;
        *(float4*)(cp)     = make_float4(out[0], out[1], out[2], out[3]);
        *(float4*)(cp + 4) = make_float4(out[4], out[5], out[6], out[7]);
    }
}

// ---------------------------------------------------------------------------
// Neighborhood attention: one warp per (b, head, s). HDIM=64 -> 2 dims/lane.
// ---------------------------------------------------------------------------
__global__ void __launch_bounds__(256)
neigh_attn_kernel(const float* __restrict__ Q, const float* __restrict__ K,
                  const float* __restrict__ V, float* __restrict__ O)
{
    int w    = (blockIdx.x * blockDim.x + threadIdx.x) >> 5;   // warp id
    int lane = threadIdx.x & 31;
    // w enumerates ((b*NHEADS + h)*SEQ + s)
    int s = w & (SEQ - 1);
    int h = (w >> 13) & (NHEADS - 1);
    int b = w >> 17;

    size_t base = ((size_t)(b * SEQ + s)) * HID + h * HDIM;
    float2 qv = *(const float2*)(Q + base + lane * 2);

    float sc[KWIN];
#pragma unroll
    for (int j = 0; j < KWIN; j++) {
        int t = s + j - KWIN / 2;
        bool valid = (t >= 0) && (t < SEQ);
        float p = 0.0f;
        if (valid) {
            size_t kb = ((size_t)(b * SEQ + t)) * HID + h * HDIM;
            float2 kv = *(const float2*)(K + kb + lane * 2);
            p = qv.x * kv.x + qv.y * kv.y;
        }
#pragma unroll
        for (int o = 16; o > 0; o >>= 1)
            p += __shfl_xor_sync(0xffffffffu, p, o);
        sc[j] = valid ? p * ATT_SCALE : -INFINITY;
    }

    float mx = sc[0];
#pragma unroll
    for (int j = 1; j < KWIN; j++) mx = fmaxf(mx, sc[j]);
    float e[KWIN], den = 0.0f;
#pragma unroll
    for (int j = 0; j < KWIN; j++) { e[j] = expf(sc[j] - mx); den += e[j]; }
    float inv = 1.0f / den;

    float2 o2 = make_float2(0.0f, 0.0f);
#pragma unroll
    for (int j = 0; j < KWIN; j++) {
        int t = s + j - KWIN / 2;
        if (t >= 0 && t < SEQ) {
            size_t vb = ((size_t)(b * SEQ + t)) * HID + h * HDIM;
            float2 vv = *(const float2*)(V + vb + lane * 2);
            float wgt = e[j] * inv;
            o2.x += wgt * vv.x;
            o2.y += wgt * vv.y;
        }
    }
    *(float2*)(O + base + lane * 2) = o2;
}

// ---------------------------------------------------------------------------
// Launch
// ---------------------------------------------------------------------------
extern "C" void kernel_launch(void* const* d_in, const int* in_sizes, int n_in,
                              void* d_out, int out_size)
{
    const float* hs  = (const float*)d_in[0];
    const float* w_q = (const float*)d_in[1];
    const float* b_q = (const float*)d_in[2];
    const float* w_k = (const float*)d_in[3];
    const float* b_k = (const float*)d_in[4];
    const float* w_v = (const float*)d_in[5];
    const float* b_v = (const float*)d_in[6];
    const float* w_o = (const float*)d_in[7];
    const float* b_o = (const float*)d_in[8];
    float* out = (float*)d_out;

    float *qb, *kb, *vb, *ab;
    cudaGetSymbolAddress((void**)&qb, g_q);
    cudaGetSymbolAddress((void**)&kb, g_k);
    cudaGetSymbolAddress((void**)&vb, g_v);
    cudaGetSymbolAddress((void**)&ab, g_attn);

    const int M = M_ROWS, N = HID, K = HID;
    dim3 gg(N / BN, M / BM);   // (8, 128)

    gemm_bias_kernel<<<gg, 256>>>(hs, w_q, b_q, qb, M, N, K);
    gemm_bias_kernel<<<gg, 256>>>(hs, w_k, b_k, kb, M, N, K);
    gemm_bias_kernel<<<gg, 256>>>(hs, w_v, b_v, vb, M, N, K);

    // one warp per (b, h, s): 2*16*8192 = 262144 warps -> 32768 blocks of 8 warps
    int total_warps = BATCH * NHEADS * SEQ;
    neigh_attn_kernel<<<total_warps / 8, 256>>>(qb, kb, vb, ab);

    gemm_bias_kernel<<<gg, 256>>>(ab, w_o, b_o, out, M, N, K);
}

// round 4
// speedup vs baseline: 1.0003x; 1.0003x over previous
#include <cuda_runtime.h>
#include <cuda_bf16.h>
#include <math.h>

// ---------------------------------------------------------------------------
// Problem constants
// ---------------------------------------------------------------------------
#define BATCH     2
#define SEQ       8192
#define HID       1024
#define NHEADS    16
#define HDIM      64
#define KWIN      7
#define ATT_SCALE 0.125f   // 1/sqrt(64)

#define M_ROWS (BATCH * SEQ)          // 16384

// Scratch (allowed: __device__ globals, no runtime allocation)
__device__ float g_q[(size_t)M_ROWS * HID];
__device__ float g_k[(size_t)M_ROWS * HID];
__device__ float g_v[(size_t)M_ROWS * HID];
__device__ float g_attn[(size_t)M_ROWS * HID];

// ---------------------------------------------------------------------------
// Packed f32x2 helpers (FFMA2 — not emitted by ptxas from C++)
// ---------------------------------------------------------------------------
__device__ __forceinline__ unsigned long long f2_dup(float x) {
    unsigned long long r;
    asm("mov.b64 %0, {%1, %1};" : "=l"(r) : "f"(x));
    return r;
}
__device__ __forceinline__ unsigned long long f2_pack(float x, float y) {
    unsigned long long r;
    asm("mov.b64 %0, {%1, %2};" : "=l"(r) : "f"(x), "f"(y));
    return r;
}
__device__ __forceinline__ unsigned long long f2_fma(unsigned long long a,
                                                     unsigned long long b,
                                                     unsigned long long c) {
    unsigned long long d;
    asm("fma.rn.f32x2 %0, %1, %2, %3;" : "=l"(d) : "l"(a), "l"(b), "l"(c));
    return d;
}
__device__ __forceinline__ float2 f2_unpack(unsigned long long p) {
    float2 v;
    asm("mov.b64 {%0, %1}, %2;" : "=f"(v.x), "=f"(v.y) : "l"(p));
    return v;
}

// ---------------------------------------------------------------------------
// GEMM: C[M,N] = A[M,K] @ B[K,N] + bias[N]
// A row-major, B row-major, C row-major. M%128==0, N%128==0, K%16==0.
// 128x128 tile, BK=16, 256 threads, 8x8 per-thread tile, packed-f32x2 FMAs.
// ---------------------------------------------------------------------------
#define BM 128
#define BN 128
#define BK 16
#define TM 8
#define TN 8

__global__ void __launch_bounds__(256, 2)
gemm_bias_kernel(const float* __restrict__ A, const float* __restrict__ B,
                 const float* __restrict__ bias, float* __restrict__ C,
                 int M, int N, int K)
{
    __shared__ float As[BK][BM];   // A tile, transposed (k-major rows)
    __shared__ float Bs[BK][BN];

    const int tid = threadIdx.x;
    const int tx  = tid & 15;      // 0..15 -> N
    const int ty  = tid >> 4;      // 0..15 -> M
    const int m0  = blockIdx.y * BM;
    const int n0  = blockIdx.x * BN;

    const float* Ab = A + (size_t)m0 * K;
    const float* Bb = B + n0;

    unsigned long long acc[TM][TN / 2];
#pragma unroll
    for (int i = 0; i < TM; i++)
#pragma unroll
        for (int j = 0; j < TN / 2; j++) acc[i][j] = 0ULL;

    for (int kt = 0; kt < K; kt += BK) {
        // --- load A tile 128x16 (transpose into As[k][m]) ---
#pragma unroll
        for (int r = 0; r < 2; r++) {
            int idx = tid + r * 256;           // 0..511 float4s
            int row = idx >> 2;                // 0..127
            int c4  = (idx & 3) << 2;          // 0,4,8,12
            float4 av = *(const float4*)(Ab + (size_t)row * K + kt + c4);
            As[c4 + 0][row] = av.x;
            As[c4 + 1][row] = av.y;
            As[c4 + 2][row] = av.z;
            As[c4 + 3][row] = av.w;
        }
        // --- load B tile 16x128 (direct) ---
#pragma unroll
        for (int r = 0; r < 2; r++) {
            int idx = tid + r * 256;
            int row = idx >> 5;                // 0..15
            int c4  = (idx & 31) << 2;         // 0..124
            *(float4*)&Bs[row][c4] =
                *(const float4*)(Bb + (size_t)(kt + row) * N + c4);
        }
        __syncthreads();

#pragma unroll
        for (int kk = 0; kk < BK; kk++) {
            float4 a0 = *(const float4*)&As[kk][ty * 8];
            float4 a4 = *(const float4*)&As[kk][ty * 8 + 4];
            float4 b0 = *(const float4*)&Bs[kk][tx * 8];
            float4 b4 = *(const float4*)&Bs[kk][tx * 8 + 4];

            unsigned long long bp[4];
            bp[0] = f2_pack(b0.x, b0.y);
            bp[1] = f2_pack(b0.z, b0.w);
            bp[2] = f2_pack(b4.x, b4.y);
            bp[3] = f2_pack(b4.z, b4.w);

            float av[TM] = {a0.x, a0.y, a0.z, a0.w, a4.x, a4.y, a4.z, a4.w};
#pragma unroll
            for (int i = 0; i < TM; i++) {
                unsigned long long ai = f2_dup(av[i]);
#pragma unroll
                for (int j = 0; j < TN / 2; j++)
                    acc[i][j] = f2_fma(ai, bp[j], acc[i][j]);
            }
        }
        __syncthreads();
    }

    // --- epilogue: unpack, add bias, store ---
    float bv[TN];
#pragma unroll
    for (int j = 0; j < TN; j++) bv[j] = bias[n0 + tx * 8 + j];

#pragma unroll
    for (int i = 0; i < TM; i++) {
        int row = m0 + ty * 8 + i;
        float out[TN];
#pragma unroll
        for (int j = 0; j < TN / 2; j++) {
            float2 v = f2_unpack(acc[i][j]);
            out[2 * j]     = v.x + bv[2 * j];
            out[2 * j + 1] = v.y + bv[2 * j + 1];
        }
        float* cp = C + (size_t)row * N + n0 + tx * 8;
        *(float4*)(cp)     = make_float4(out[0], out[1], out[2], out[3]);
        *(float4*)(cp + 4) = make_float4(out[4], out[5], out[6], out[7]);
    }
}

// ---------------------------------------------------------------------------
// Neighborhood attention: one warp per (b, head, s). HDIM=64 -> 2 dims/lane.
// ---------------------------------------------------------------------------
__global__ void __launch_bounds__(256)
neigh_attn_kernel(const float* __restrict__ Q, const float* __restrict__ K,
                  const float* __restrict__ V, float* __restrict__ O)
{
    int w    = (blockIdx.x * blockDim.x + threadIdx.x) >> 5;   // warp id
    int lane = threadIdx.x & 31;
    // w enumerates ((b*NHEADS + h)*SEQ + s)
    int s = w & (SEQ - 1);
    int h = (w >> 13) & (NHEADS - 1);
    int b = w >> 17;

    size_t base = ((size_t)(b * SEQ + s)) * HID + h * HDIM;
    float2 qv = *(const float2*)(Q + base + lane * 2);

    float sc[KWIN];
#pragma unroll
    for (int j = 0; j < KWIN; j++) {
        int t = s + j - KWIN / 2;
        bool valid = (t >= 0) && (t < SEQ);
        float p = 0.0f;
        if (valid) {
            size_t kb = ((size_t)(b * SEQ + t)) * HID + h * HDIM;
            float2 kv = *(const float2*)(K + kb + lane * 2);
            p = qv.x * kv.x + qv.y * kv.y;
        }
#pragma unroll
        for (int o = 16; o > 0; o >>= 1)
            p += __shfl_xor_sync(0xffffffffu, p, o);
        sc[j] = valid ? p * ATT_SCALE : -INFINITY;
    }

    float mx = sc[0];
#pragma unroll
    for (int j = 1; j < KWIN; j++) mx = fmaxf(mx, sc[j]);
    float e[KWIN], den = 0.0f;
#pragma unroll
    for (int j = 0; j < KWIN; j++) { e[j] = expf(sc[j] - mx); den += e[j]; }
    float inv = 1.0f / den;

    float2 o2 = make_float2(0.0f, 0.0f);
#pragma unroll
    for (int j = 0; j < KWIN; j++) {
        int t = s + j - KWIN / 2;
        if (t >= 0 && t < SEQ) {
            size_t vb = ((size_t)(b * SEQ + t)) * HID + h * HDIM;
            float2 vv = *(const float2*)(V + vb + lane * 2);
            float wgt = e[j] * inv;
            o2.x += wgt * vv.x;
            o2.y += wgt * vv.y;
        }
    }
    *(float2*)(O + base + lane * 2) = o2;
}

// ---------------------------------------------------------------------------
// Launch
// ---------------------------------------------------------------------------
extern "C" void kernel_launch(void* const* d_in, const int* in_sizes, int n_in,
                              void* d_out, int out_size)
{
    const float* hs  = (const float*)d_in[0];
    const float* w_q = (const float*)d_in[1];
    const float* b_q = (const float*)d_in[2];
    const float* w_k = (const float*)d_in[3];
    const float* b_k = (const float*)d_in[4];
    const float* w_v = (const float*)d_in[5];
    const float* b_v = (const float*)d_in[6];
    const float* w_o = (const float*)d_in[7];
    const float* b_o = (const float*)d_in[8];
    float* out = (float*)d_out;

    float *qb, *kb, *vb, *ab;
    cudaGetSymbolAddress((void**)&qb, g_q);
    cudaGetSymbolAddress((void**)&kb, g_k);
    cudaGetSymbolAddress((void**)&vb, g_v);
    cudaGetSymbolAddress((void**)&ab, g_attn);

    const int M = M_ROWS, N = HID, K = HID;
    dim3 gg(N / BN, M / BM);   // (8, 128)

    gemm_bias_kernel<<<gg, 256>>>(hs, w_q, b_q, qb, M, N, K);
    gemm_bias_kernel<<<gg, 256>>>(hs, w_k, b_k, kb, M, N, K);
    gemm_bias_kernel<<<gg, 256>>>(hs, w_v, b_v, vb, M, N, K);

    // one warp per (b, h, s): 2*16*8192 = 262144 warps -> 32768 blocks of 8 warps
    int total_warps = BATCH * NHEADS * SEQ;
    neigh_attn_kernel<<<total_warps / 8, 256>>>(qb, kb, vb, ab);

    gemm_bias_kernel<<<gg, 256>>>(ab, w_o, b_o, out, M, N, K);
}

// round 6
// speedup vs baseline: 2.1683x; 2.1675x over previous
#include <cuda_runtime.h>
#include <cuda_bf16.h>
#include <math.h>
#include <stdint.h>

// ---------------------------------------------------------------------------
// Problem constants
// ---------------------------------------------------------------------------
#define BATCH     2
#define SEQ       8192
#define HID       1024
#define NHEADS    16
#define HDIM      64
#define KWIN      7
#define ATT_SCALE 0.125f
#define M_ROWS    (BATCH * SEQ)     // 16384

// ---------------------------------------------------------------------------
// Scratch (__device__ globals: allowed, no runtime allocation)
// ---------------------------------------------------------------------------
__device__ float g_q[(size_t)M_ROWS * HID];
__device__ float g_k[(size_t)M_ROWS * HID];
__device__ float g_v[(size_t)M_ROWS * HID];
__device__ float g_attn[(size_t)M_ROWS * HID];
__device__ __nv_bfloat16 g_a_hi[(size_t)M_ROWS * HID];
__device__ __nv_bfloat16 g_a_lo[(size_t)M_ROWS * HID];
__device__ __nv_bfloat16 g_w_hi[(size_t)4 * HID * HID];   // transposed [n][k], 4 mats
__device__ __nv_bfloat16 g_w_lo[(size_t)4 * HID * HID];

// ---------------------------------------------------------------------------
// PTX helpers (base sm_103 target — NO 'a'-gated features)
// ---------------------------------------------------------------------------
__device__ __forceinline__ uint32_t smem_u32(const void* p) {
    uint32_t a;
    asm("{ .reg .u64 t; cvta.to.shared.u64 t, %1; cvt.u32.u64 %0, t; }"
        : "=r"(a) : "l"(p));
    return a;
}
__device__ __forceinline__ void cp16(uint32_t s, const void* g) {
    asm volatile("cp.async.cg.shared.global [%0], [%1], 16;"
                 :: "r"(s), "l"(g));
}
__device__ __forceinline__ void ldsm_x4(uint32_t* r, uint32_t addr) {
    asm volatile("ldmatrix.sync.aligned.m8n8.x4.shared.b16 {%0,%1,%2,%3}, [%4];"
                 : "=r"(r[0]), "=r"(r[1]), "=r"(r[2]), "=r"(r[3]) : "r"(addr));
}
__device__ __forceinline__ void mma16816(float* d, const uint32_t* a,
                                         const uint32_t* b) {
    asm volatile(
        "mma.sync.aligned.m16n8k16.row.col.f32.bf16.bf16.f32 "
        "{%0,%1,%2,%3}, {%4,%5,%6,%7}, {%8,%9}, {%0,%1,%2,%3};"
        : "+f"(d[0]), "+f"(d[1]), "+f"(d[2]), "+f"(d[3])
        : "r"(a[0]), "r"(a[1]), "r"(a[2]), "r"(a[3]), "r"(b[0]), "r"(b[1]));
}

// ---------------------------------------------------------------------------
// GEMM config: 128x128 CTA tile, BK=32, double-buffered cp.async
// ---------------------------------------------------------------------------
#define PITCH   80                     // bytes per 32-elem bf16 row (64 + 16 pad)
#define TILEB   (128 * PITCH)          // 10240 per tile
#define OFF_AL  TILEB
#define OFF_BH  (2 * TILEB)
#define OFF_BL  (3 * TILEB)
#define BUFB    (4 * TILEB)            // 40960 per buffer
#define SMEMB   (2 * BUFB)             // 81920 total

__device__ __forceinline__ void load_chunk(
    uint32_t base, int tid, int k0, int m0, int n0,
    const __nv_bfloat16* __restrict__ Ah, const __nv_bfloat16* __restrict__ Al,
    const __nv_bfloat16* __restrict__ Bh, const __nv_bfloat16* __restrict__ Bl)
{
#pragma unroll
    for (int r = 0; r < 2; r++) {
        int idx = tid + r * 256;          // 0..511
        int row = idx >> 2;               // 0..127
        int c   = idx & 3;                // 16B chunk within 64B row
        uint32_t so = (uint32_t)(row * PITCH + c * 16);
        size_t goA = (size_t)(m0 + row) * HID + k0 + c * 8;
        size_t goB = (size_t)(n0 + row) * HID + k0 + c * 8;
        cp16(base + so,          Ah + goA);
        cp16(base + OFF_AL + so, Al + goA);
        cp16(base + OFF_BH + so, Bh + goB);
        cp16(base + OFF_BL + so, Bl + goB);
    }
    asm volatile("cp.async.commit_group;" ::: "memory");
}

// C[m][n] = sum_k A[m][k]*Bt[n][k] + bias[n], via 3-pass bf16 split HMMA.
// Up to 3 weight matrices per launch: matrix = mat_base + blockIdx.x/8.
__global__ void __launch_bounds__(256, 1)
gemm_mma(const __nv_bfloat16* __restrict__ Ah, const __nv_bfloat16* __restrict__ Al,
         const __nv_bfloat16* __restrict__ Wh, const __nv_bfloat16* __restrict__ Wl,
         int mat_base,
         const float* __restrict__ bias0, const float* __restrict__ bias1,
         const float* __restrict__ bias2,
         float* __restrict__ c0, float* __restrict__ c1, float* __restrict__ c2)
{
    extern __shared__ char smem[];
    const uint32_t sb = smem_u32(smem);
    const int tid  = threadIdx.x;
    const int lane = tid & 31;
    const int wid  = tid >> 5;
    const int wm   = wid >> 2;          // 0..1 -> 64-row slab
    const int wn   = wid & 3;           // 0..3 -> 32-col slab
    const int mi_  = blockIdx.x >> 3;   // matrix within launch
    const int n0   = (blockIdx.x & 7) * 128;
    const int m0   = blockIdx.y * 128;

    const __nv_bfloat16* Bh = Wh + (size_t)(mat_base + mi_) * HID * HID;
    const __nv_bfloat16* Bl = Wl + (size_t)(mat_base + mi_) * HID * HID;
    const float* bias = (mi_ == 0) ? bias0 : ((mi_ == 1) ? bias1 : bias2);
    float* C = (mi_ == 0) ? c0 : ((mi_ == 1) ? c1 : c2);

    float acc[4][4][4];
#pragma unroll
    for (int i = 0; i < 4; i++)
#pragma unroll
        for (int j = 0; j < 4; j++)
#pragma unroll
            for (int r = 0; r < 4; r++) acc[i][j][r] = 0.0f;

    // prologue: fill both buffers
    load_chunk(sb,        tid, 0,  m0, n0, Ah, Al, Bh, Bl);
    load_chunk(sb + BUFB, tid, 32, m0, n0, Ah, Al, Bh, Bl);

    // per-thread ldmatrix source offsets (x4: lanes 8m..8m+7 address matrix m)
    const int mrow = lane >> 3;         // which 8x8 matrix
    const int jrow = lane & 7;
    // A x4: m0=(r0-7,k0-7) m1=(r8-15,k0-7) m2=(r0-7,k8-15) m3=(r8-15,k8-15)
    const uint32_t a_off = (uint32_t)((wm * 64 + (mrow & 1) * 8 + jrow) * PITCH
                                      + (mrow >> 1) * 16);
    // B x4: m0=(n0-7,k0-7) m1=(n0-7,k8-15) m2=(n8-15,k0-7) m3=(n8-15,k8-15)
    const uint32_t b_off = (uint32_t)((wn * 32 + (mrow >> 1) * 8 + jrow) * PITCH
                                      + (mrow & 1) * 16) + OFF_BH;

    for (int ck = 0; ck < 32; ck++) {
        if (ck == 31) asm volatile("cp.async.wait_group 0;" ::: "memory");
        else          asm volatile("cp.async.wait_group 1;" ::: "memory");
        __syncthreads();

        const uint32_t base = sb + (ck & 1) * BUFB;
#pragma unroll
        for (int ks = 0; ks < 2; ks++) {
            const uint32_t kb = ks * 32;   // byte offset of k-step within row
            uint32_t ah[4][4], al[4][4], bh[2][4], bl[2][4];
#pragma unroll
            for (int mi = 0; mi < 4; mi++) {
                uint32_t ad = base + a_off + mi * 16 * PITCH + kb;
                ldsm_x4(ah[mi], ad);
                ldsm_x4(al[mi], ad + OFF_AL);
            }
#pragma unroll
            for (int nj = 0; nj < 2; nj++) {
                uint32_t bd = base + b_off + nj * 16 * PITCH + kb;
                ldsm_x4(bh[nj], bd);
                ldsm_x4(bl[nj], bd + TILEB);   // OFF_BL - OFF_BH
            }
#pragma unroll
            for (int mi = 0; mi < 4; mi++)
#pragma unroll
                for (int ni = 0; ni < 4; ni++) {
                    const uint32_t* ph = &bh[ni >> 1][(ni & 1) * 2];
                    const uint32_t* pl = &bl[ni >> 1][(ni & 1) * 2];
                    mma16816(acc[mi][ni], ah[mi], ph);   // Ah*Bh
                    mma16816(acc[mi][ni], ah[mi], pl);   // Ah*Bl
                    mma16816(acc[mi][ni], al[mi], ph);   // Al*Bh
                }
        }
        __syncthreads();
        if (ck + 2 < 32)
            load_chunk(sb + (ck & 1) * BUFB, tid, (ck + 2) * 32, m0, n0,
                       Ah, Al, Bh, Bl);
    }

    // epilogue: fragment layout -> C, add bias
    const int grp = lane >> 2, t4 = lane & 3;
#pragma unroll
    for (int ni = 0; ni < 4; ni++) {
        const int col = n0 + wn * 32 + ni * 8 + t4 * 2;
        const float bv0 = bias[col], bv1 = bias[col + 1];
#pragma unroll
        for (int mi = 0; mi < 4; mi++) {
            const int r0 = m0 + wm * 64 + mi * 16 + grp;
            *(float2*)(C + (size_t)r0 * HID + col) =
                make_float2(acc[mi][ni][0] + bv0, acc[mi][ni][1] + bv1);
            *(float2*)(C + (size_t)(r0 + 8) * HID + col) =
                make_float2(acc[mi][ni][2] + bv0, acc[mi][ni][3] + bv1);
        }
    }
}

// ---------------------------------------------------------------------------
// Decompose fp32 -> bf16 hi + bf16 lo (elementwise)
// ---------------------------------------------------------------------------
__global__ void __launch_bounds__(256)
decompose_act(const float* __restrict__ x,
              __nv_bfloat16* __restrict__ hi, __nv_bfloat16* __restrict__ lo)
{
    size_t i = ((size_t)blockIdx.x * 256 + threadIdx.x) * 4;
    float4 v = *(const float4*)(x + i);
    float f[4] = {v.x, v.y, v.z, v.w};
    unsigned short hs[4], ls[4];
#pragma unroll
    for (int j = 0; j < 4; j++) {
        __nv_bfloat16 h = __float2bfloat16(f[j]);
        __nv_bfloat16 l = __float2bfloat16(f[j] - __bfloat162float(h));
        hs[j] = __bfloat16_as_ushort(h);
        ls[j] = __bfloat16_as_ushort(l);
    }
    uint2 H = make_uint2(hs[0] | ((unsigned)hs[1] << 16),
                         hs[2] | ((unsigned)hs[3] << 16));
    uint2 L = make_uint2(ls[0] | ((unsigned)ls[1] << 16),
                         ls[2] | ((unsigned)ls[3] << 16));
    *(uint2*)(hi + i) = H;
    *(uint2*)(lo + i) = L;
}

// ---------------------------------------------------------------------------
// Transpose + decompose weights: Wt[n][k] = W[k][n], 4 matrices (z-dim)
// ---------------------------------------------------------------------------
__global__ void __launch_bounds__(256)
decompose_w(const float* __restrict__ w0, const float* __restrict__ w1,
            const float* __restrict__ w2, const float* __restrict__ w3,
            __nv_bfloat16* __restrict__ hi, __nv_bfloat16* __restrict__ lo)
{
    __shared__ float t[32][33];
    const int z = blockIdx.z;
    const float* W = (z == 0) ? w0 : ((z == 1) ? w1 : ((z == 2) ? w2 : w3));
    const int n0 = blockIdx.x * 32, k0 = blockIdx.y * 32;
    const int tx = threadIdx.x & 31, ty = threadIdx.x >> 5;   // 32 x 8
#pragma unroll
    for (int r = 0; r < 4; r++)
        t[ty + r * 8][tx] = W[(size_t)(k0 + ty + r * 8) * HID + n0 + tx];
    __syncthreads();
    const size_t base = (size_t)z * HID * HID;
#pragma unroll
    for (int r = 0; r < 4; r++) {
        int n = n0 + ty + r * 8;
        int k = k0 + tx;
        float v = t[tx][ty + r * 8];
        __nv_bfloat16 h = __float2bfloat16(v);
        __nv_bfloat16 l = __float2bfloat16(v - __bfloat162float(h));
        hi[base + (size_t)n * HID + k] = h;
        lo[base + (size_t)n * HID + k] = l;
    }
}

// ---------------------------------------------------------------------------
// Neighborhood attention: one warp per (b, head, s). HDIM=64 -> 2 dims/lane.
// ---------------------------------------------------------------------------
__global__ void __launch_bounds__(256)
neigh_attn_kernel(const float* __restrict__ Q, const float* __restrict__ K,
                  const float* __restrict__ V, float* __restrict__ O)
{
    int w    = (blockIdx.x * blockDim.x + threadIdx.x) >> 5;
    int lane = threadIdx.x & 31;
    int s = w & (SEQ - 1);
    int h = (w >> 13) & (NHEADS - 1);
    int b = w >> 17;

    size_t base = ((size_t)(b * SEQ + s)) * HID + h * HDIM;
    float2 qv = *(const float2*)(Q + base + lane * 2);

    float sc[KWIN];
#pragma unroll
    for (int j = 0; j < KWIN; j++) {
        int t = s + j - KWIN / 2;
        bool valid = (t >= 0) && (t < SEQ);
        float p = 0.0f;
        if (valid) {
            size_t kb = ((size_t)(b * SEQ + t)) * HID + h * HDIM;
            float2 kv = *(const float2*)(K + kb + lane * 2);
            p = qv.x * kv.x + qv.y * kv.y;
        }
#pragma unroll
        for (int o = 16; o > 0; o >>= 1)
            p += __shfl_xor_sync(0xffffffffu, p, o);
        sc[j] = valid ? p * ATT_SCALE : -INFINITY;
    }

    float mx = sc[0];
#pragma unroll
    for (int j = 1; j < KWIN; j++) mx = fmaxf(mx, sc[j]);
    float e[KWIN], den = 0.0f;
#pragma unroll
    for (int j = 0; j < KWIN; j++) { e[j] = expf(sc[j] - mx); den += e[j]; }
    float inv = 1.0f / den;

    float2 o2 = make_float2(0.0f, 0.0f);
#pragma unroll
    for (int j = 0; j < KWIN; j++) {
        int t = s + j - KWIN / 2;
        if (t >= 0 && t < SEQ) {
            size_t vb = ((size_t)(b * SEQ + t)) * HID + h * HDIM;
            float2 vv = *(const float2*)(V + vb + lane * 2);
            float wgt = e[j] * inv;
            o2.x += wgt * vv.x;
            o2.y += wgt * vv.y;
        }
    }
    *(float2*)(O + base + lane * 2) = o2;
}

// ---------------------------------------------------------------------------
// Launch
// ---------------------------------------------------------------------------
extern "C" void kernel_launch(void* const* d_in, const int* in_sizes, int n_in,
                              void* d_out, int out_size)
{
    const float* hs  = (const float*)d_in[0];
    const float* w_q = (const float*)d_in[1];
    const float* b_q = (const float*)d_in[2];
    const float* w_k = (const float*)d_in[3];
    const float* b_k = (const float*)d_in[4];
    const float* w_v = (const float*)d_in[5];
    const float* b_v = (const float*)d_in[6];
    const float* w_o = (const float*)d_in[7];
    const float* b_o = (const float*)d_in[8];
    float* out = (float*)d_out;

    float *qb, *kb, *vb, *ab;
    __nv_bfloat16 *ah, *al, *wh, *wl;
    cudaGetSymbolAddress((void**)&qb, g_q);
    cudaGetSymbolAddress((void**)&kb, g_k);
    cudaGetSymbolAddress((void**)&vb, g_v);
    cudaGetSymbolAddress((void**)&ab, g_attn);
    cudaGetSymbolAddress((void**)&ah, g_a_hi);
    cudaGetSymbolAddress((void**)&al, g_a_lo);
    cudaGetSymbolAddress((void**)&wh, g_w_hi);
    cudaGetSymbolAddress((void**)&wl, g_w_lo);

    cudaFuncSetAttribute(gemm_mma, cudaFuncAttributeMaxDynamicSharedMemorySize,
                         SMEMB);

    const int act_blocks = (M_ROWS * HID) / (256 * 4);   // 16384

    // 1) decompose activations + weights
    decompose_act<<<act_blocks, 256>>>(hs, ah, al);
    decompose_w<<<dim3(32, 32, 4), 256>>>(w_q, w_k, w_v, w_o, wh, wl);

    // 2) fused QKV GEMM: 3 matrices x 8 N-tiles, 128 M-tiles
    gemm_mma<<<dim3(24, 128), 256, SMEMB>>>(
        ah, al, wh, wl, 0, b_q, b_k, b_v, qb, kb, vb);

    // 3) neighborhood attention
    neigh_attn_kernel<<<(BATCH * NHEADS * SEQ) / 8, 256>>>(qb, kb, vb, ab);

    // 4) decompose attention output, then O projection
    decompose_act<<<act_blocks, 256>>>(ab, ah, al);
    gemm_mma<<<dim3(8, 128), 256, SMEMB>>>(
        ah, al, wh, wl, 3, b_o, b_o, b_o, out, out, out);
}

// round 7
// speedup vs baseline: 2.3189x; 1.0695x over previous
#include <cuda_runtime.h>
#include <cuda_bf16.h>
#include <math.h>
#include <stdint.h>

// ---------------------------------------------------------------------------
// Problem constants
// ---------------------------------------------------------------------------
#define BATCH     2
#define SEQ       8192
#define HID       1024
#define NHEADS    16
#define HDIM      64
#define KWIN      7
#define ATT_SCALE 0.125f
#define M_ROWS    (BATCH * SEQ)     // 16384

// ---------------------------------------------------------------------------
// Scratch (__device__ globals: allowed, no runtime allocation)
// ---------------------------------------------------------------------------
__device__ float g_q[(size_t)M_ROWS * HID];
__device__ float g_k[(size_t)M_ROWS * HID];
__device__ float g_v[(size_t)M_ROWS * HID];
__device__ __nv_bfloat16 g_a_hi[(size_t)M_ROWS * HID];
__device__ __nv_bfloat16 g_a_lo[(size_t)M_ROWS * HID];
__device__ __nv_bfloat16 g_o_hi[(size_t)M_ROWS * HID];   // attention out hi
__device__ __nv_bfloat16 g_o_lo[(size_t)M_ROWS * HID];   // attention out lo
__device__ __nv_bfloat16 g_w_hi[(size_t)4 * HID * HID];  // transposed [n][k]
__device__ __nv_bfloat16 g_w_lo[(size_t)4 * HID * HID];

// ---------------------------------------------------------------------------
// PTX helpers (base sm_103 target — NO 'a'-gated features)
// ---------------------------------------------------------------------------
__device__ __forceinline__ uint32_t smem_u32(const void* p) {
    uint32_t a;
    asm("{ .reg .u64 t; cvta.to.shared.u64 t, %1; cvt.u32.u64 %0, t; }"
        : "=r"(a) : "l"(p));
    return a;
}
__device__ __forceinline__ void cp16(uint32_t s, const void* g) {
    asm volatile("cp.async.cg.shared.global [%0], [%1], 16;"
                 :: "r"(s), "l"(g));
}
__device__ __forceinline__ void ldsm_x4(uint32_t* r, uint32_t addr) {
    asm volatile("ldmatrix.sync.aligned.m8n8.x4.shared.b16 {%0,%1,%2,%3}, [%4];"
                 : "=r"(r[0]), "=r"(r[1]), "=r"(r[2]), "=r"(r[3]) : "r"(addr));
}
__device__ __forceinline__ void mma16816(float* d, const uint32_t* a,
                                         const uint32_t* b) {
    asm volatile(
        "mma.sync.aligned.m16n8k16.row.col.f32.bf16.bf16.f32 "
        "{%0,%1,%2,%3}, {%4,%5,%6,%7}, {%8,%9}, {%0,%1,%2,%3};"
        : "+f"(d[0]), "+f"(d[1]), "+f"(d[2]), "+f"(d[3])
        : "r"(a[0]), "r"(a[1]), "r"(a[2]), "r"(a[3]), "r"(b[0]), "r"(b[1]));
}

// ---------------------------------------------------------------------------
// GEMM config: 128x256 CTA tile, BK=32, 3-stage cp.async ring, 512 threads
// ---------------------------------------------------------------------------
#define PITCH   80                      // bytes per 32-elem bf16 row (64+16 pad)
#define TILE_A  (128 * PITCH)           // 10240
#define TILE_B  (256 * PITCH)           // 20480
#define OFF_AL  TILE_A                  // 10240
#define OFF_BH  (2 * TILE_A)            // 20480
#define OFF_BL  (2 * TILE_A + TILE_B)   // 40960
#define BUFB    (2 * TILE_A + 2 * TILE_B)   // 61440 per stage
#define NSTAGE  3
#define SMEMB   (NSTAGE * BUFB)         // 184320

__device__ __forceinline__ void load_chunk(
    uint32_t base, int tid, int k0, int m0, int n0,
    const __nv_bfloat16* __restrict__ Ah, const __nv_bfloat16* __restrict__ Al,
    const __nv_bfloat16* __restrict__ Bh, const __nv_bfloat16* __restrict__ Bl)
{
    {   // A hi/lo: 128 rows x 64B, 512 threads -> 1 cp16 each per tile
        int row = tid >> 2, c = tid & 3;
        uint32_t so = (uint32_t)(row * PITCH + c * 16);
        size_t go = (size_t)(m0 + row) * HID + k0 + c * 8;
        cp16(base + so,          Ah + go);
        cp16(base + OFF_AL + so, Al + go);
    }
#pragma unroll
    for (int r = 0; r < 2; r++) {   // B hi/lo: 256 rows x 64B
        int idx = tid + r * 512;
        int row = idx >> 2, c = idx & 3;
        uint32_t so = (uint32_t)(row * PITCH + c * 16);
        size_t go = (size_t)(n0 + row) * HID + k0 + c * 8;
        cp16(base + OFF_BH + so, Bh + go);
        cp16(base + OFF_BL + so, Bl + go);
    }
    asm volatile("cp.async.commit_group;" ::: "memory");
}

// C[m][n] = sum_k A[m][k]*Bt[n][k] + bias[n], 3-pass bf16 split HMMA.
// grid.x: (matrix_within_launch << 2) | n_tile;  grid.y: m_tile
__global__ void __launch_bounds__(512, 1)
gemm_mma(const __nv_bfloat16* __restrict__ Ah, const __nv_bfloat16* __restrict__ Al,
         const __nv_bfloat16* __restrict__ Wh, const __nv_bfloat16* __restrict__ Wl,
         int mat_base,
         const float* __restrict__ bias0, const float* __restrict__ bias1,
         const float* __restrict__ bias2,
         float* __restrict__ c0, float* __restrict__ c1, float* __restrict__ c2)
{
    extern __shared__ char smem[];
    const uint32_t sb = smem_u32(smem);
    const int tid  = threadIdx.x;
    const int lane = tid & 31;
    const int wid  = tid >> 5;          // 0..15
    const int wm   = wid >> 3;          // 0..1 -> 64-row slab
    const int wn   = wid & 7;           // 0..7 -> 32-col slab
    const int mi_  = blockIdx.x >> 2;   // matrix within launch
    const int n0   = (blockIdx.x & 3) * 256;
    const int m0   = blockIdx.y * 128;

    const __nv_bfloat16* Bh = Wh + (size_t)(mat_base + mi_) * HID * HID;
    const __nv_bfloat16* Bl = Wl + (size_t)(mat_base + mi_) * HID * HID;
    const float* bias = (mi_ == 0) ? bias0 : ((mi_ == 1) ? bias1 : bias2);
    float* C = (mi_ == 0) ? c0 : ((mi_ == 1) ? c1 : c2);

    float acc[4][4][4];
#pragma unroll
    for (int i = 0; i < 4; i++)
#pragma unroll
        for (int j = 0; j < 4; j++)
#pragma unroll
            for (int r = 0; r < 4; r++) acc[i][j][r] = 0.0f;

    // prologue: stages 0,1
    load_chunk(sb,        tid, 0,  m0, n0, Ah, Al, Bh, Bl);
    load_chunk(sb + BUFB, tid, 32, m0, n0, Ah, Al, Bh, Bl);

    // per-thread ldmatrix source offsets (identical to verified R6 layout)
    const int mrow = lane >> 3;
    const int jrow = lane & 7;
    const uint32_t a_off = (uint32_t)((wm * 64 + (mrow & 1) * 8 + jrow) * PITCH
                                      + (mrow >> 1) * 16);
    const uint32_t b_off = (uint32_t)((wn * 32 + (mrow >> 1) * 8 + jrow) * PITCH
                                      + (mrow & 1) * 16) + OFF_BH;

    const int NCHUNK = HID / 32;        // 32
    uint32_t stage_base[NSTAGE] = {sb, sb + BUFB, sb + 2 * BUFB};
    int st = 0;                         // stage of current chunk

    for (int ck = 0; ck < NCHUNK; ck++) {
        if (ck < NCHUNK - 2) asm volatile("cp.async.wait_group 1;" ::: "memory");
        else                 asm volatile("cp.async.wait_group 0;" ::: "memory");
        __syncthreads();   // chunk ck visible; all warps done with chunk ck-1

        // prefetch chunk ck+2 into the stage freed at iter ck-1
        if (ck + 2 < NCHUNK) {
            int ls = st + 2; if (ls >= NSTAGE) ls -= NSTAGE;
            load_chunk(stage_base[ls], tid, (ck + 2) * 32, m0, n0,
                       Ah, Al, Bh, Bl);
        }

        const uint32_t base = stage_base[st];
#pragma unroll
        for (int ks = 0; ks < 2; ks++) {
            const uint32_t kb = ks * 32;
            uint32_t bh[2][4], bl[2][4];
#pragma unroll
            for (int nj = 0; nj < 2; nj++) {
                uint32_t bd = base + b_off + nj * 16 * PITCH + kb;
                ldsm_x4(bh[nj], bd);
                ldsm_x4(bl[nj], bd + TILE_B);   // OFF_BL - OFF_BH
            }
#pragma unroll
            for (int mi = 0; mi < 4; mi++) {
                uint32_t ah[4], al[4];
                uint32_t ad = base + a_off + mi * 16 * PITCH + kb;
                ldsm_x4(ah, ad);
                ldsm_x4(al, ad + OFF_AL);
#pragma unroll
                for (int ni = 0; ni < 4; ni++) {
                    const uint32_t* ph = &bh[ni >> 1][(ni & 1) * 2];
                    const uint32_t* pl = &bl[ni >> 1][(ni & 1) * 2];
                    mma16816(acc[mi][ni], ah, ph);   // Ah*Bh
                    mma16816(acc[mi][ni], ah, pl);   // Ah*Bl
                    mma16816(acc[mi][ni], al, ph);   // Al*Bh
                }
            }
        }
        if (++st == NSTAGE) st = 0;
    }

    // epilogue: fragment layout -> C, add bias
    const int grp = lane >> 2, t4 = lane & 3;
#pragma unroll
    for (int ni = 0; ni < 4; ni++) {
        const int col = n0 + wn * 32 + ni * 8 + t4 * 2;
        const float bv0 = bias[col], bv1 = bias[col + 1];
#pragma unroll
        for (int mi = 0; mi < 4; mi++) {
            const int r0 = m0 + wm * 64 + mi * 16 + grp;
            *(float2*)(C + (size_t)r0 * HID + col) =
                make_float2(acc[mi][ni][0] + bv0, acc[mi][ni][1] + bv1);
            *(float2*)(C + (size_t)(r0 + 8) * HID + col) =
                make_float2(acc[mi][ni][2] + bv0, acc[mi][ni][3] + bv1);
        }
    }
}

// ---------------------------------------------------------------------------
// Decompose fp32 -> bf16 hi + bf16 lo (elementwise)
// ---------------------------------------------------------------------------
__global__ void __launch_bounds__(256)
decompose_act(const float* __restrict__ x,
              __nv_bfloat16* __restrict__ hi, __nv_bfloat16* __restrict__ lo)
{
    size_t i = ((size_t)blockIdx.x * 256 + threadIdx.x) * 4;
    float4 v = *(const float4*)(x + i);
    float f[4] = {v.x, v.y, v.z, v.w};
    unsigned short hs[4], ls[4];
#pragma unroll
    for (int j = 0; j < 4; j++) {
        __nv_bfloat16 h = __float2bfloat16(f[j]);
        __nv_bfloat16 l = __float2bfloat16(f[j] - __bfloat162float(h));
        hs[j] = __bfloat16_as_ushort(h);
        ls[j] = __bfloat16_as_ushort(l);
    }
    uint2 H = make_uint2(hs[0] | ((unsigned)hs[1] << 16),
                         hs[2] | ((unsigned)hs[3] << 16));
    uint2 L = make_uint2(ls[0] | ((unsigned)ls[1] << 16),
                         ls[2] | ((unsigned)ls[3] << 16));
    *(uint2*)(hi + i) = H;
    *(uint2*)(lo + i) = L;
}

// ---------------------------------------------------------------------------
// Transpose + decompose weights: Wt[n][k] = W[k][n], 4 matrices (z-dim)
// ---------------------------------------------------------------------------
__global__ void __launch_bounds__(256)
decompose_w(const float* __restrict__ w0, const float* __restrict__ w1,
            const float* __restrict__ w2, const float* __restrict__ w3,
            __nv_bfloat16* __restrict__ hi, __nv_bfloat16* __restrict__ lo)
{
    __shared__ float t[32][33];
    const int z = blockIdx.z;
    const float* W = (z == 0) ? w0 : ((z == 1) ? w1 : ((z == 2) ? w2 : w3));
    const int n0 = blockIdx.x * 32, k0 = blockIdx.y * 32;
    const int tx = threadIdx.x & 31, ty = threadIdx.x >> 5;   // 32 x 8
#pragma unroll
    for (int r = 0; r < 4; r++)
        t[ty + r * 8][tx] = W[(size_t)(k0 + ty + r * 8) * HID + n0 + tx];
    __syncthreads();
    const size_t base = (size_t)z * HID * HID;
#pragma unroll
    for (int r = 0; r < 4; r++) {
        int n = n0 + ty + r * 8;
        int k = k0 + tx;
        float v = t[tx][ty + r * 8];
        __nv_bfloat16 h = __float2bfloat16(v);
        __nv_bfloat16 l = __float2bfloat16(v - __bfloat162float(h));
        hi[base + (size_t)n * HID + k] = h;
        lo[base + (size_t)n * HID + k] = l;
    }
}

// ---------------------------------------------------------------------------
// Neighborhood attention: one warp per (b, head, s). HDIM=64 -> 2 dims/lane.
// Writes the attention output directly as bf16 hi/lo (fused decompose).
// ---------------------------------------------------------------------------
__global__ void __launch_bounds__(256)
neigh_attn_kernel(const float* __restrict__ Q, const float* __restrict__ K,
                  const float* __restrict__ V,
                  __nv_bfloat16* __restrict__ Ohi,
                  __nv_bfloat16* __restrict__ Olo)
{
    int w    = (blockIdx.x * blockDim.x + threadIdx.x) >> 5;
    int lane = threadIdx.x & 31;
    int s = w & (SEQ - 1);
    int h = (w >> 13) & (NHEADS - 1);
    int b = w >> 17;

    size_t base = ((size_t)(b * SEQ + s)) * HID + h * HDIM;
    float2 qv = *(const float2*)(Q + base + lane * 2);

    float sc[KWIN];
#pragma unroll
    for (int j = 0; j < KWIN; j++) {
        int t = s + j - KWIN / 2;
        bool valid = (t >= 0) && (t < SEQ);
        float p = 0.0f;
        if (valid) {
            size_t kb = ((size_t)(b * SEQ + t)) * HID + h * HDIM;
            float2 kv = *(const float2*)(K + kb + lane * 2);
            p = qv.x * kv.x + qv.y * kv.y;
        }
#pragma unroll
        for (int o = 16; o > 0; o >>= 1)
            p += __shfl_xor_sync(0xffffffffu, p, o);
        sc[j] = valid ? p * ATT_SCALE : -INFINITY;
    }

    float mx = sc[0];
#pragma unroll
    for (int j = 1; j < KWIN; j++) mx = fmaxf(mx, sc[j]);
    float e[KWIN], den = 0.0f;
#pragma unroll
    for (int j = 0; j < KWIN; j++) { e[j] = expf(sc[j] - mx); den += e[j]; }
    float inv = 1.0f / den;

    float2 o2 = make_float2(0.0f, 0.0f);
#pragma unroll
    for (int j = 0; j < KWIN; j++) {
        int t = s + j - KWIN / 2;
        if (t >= 0 && t < SEQ) {
            size_t vb = ((size_t)(b * SEQ + t)) * HID + h * HDIM;
            float2 vv = *(const float2*)(V + vb + lane * 2);
            float wgt = e[j] * inv;
            o2.x += wgt * vv.x;
            o2.y += wgt * vv.y;
        }
    }

    __nv_bfloat16 h0 = __float2bfloat16(o2.x);
    __nv_bfloat16 h1 = __float2bfloat16(o2.y);
    __nv_bfloat16 l0 = __float2bfloat16(o2.x - __bfloat162float(h0));
    __nv_bfloat16 l1 = __float2bfloat16(o2.y - __bfloat162float(h1));
    unsigned hiw = __bfloat16_as_ushort(h0) |
                   ((unsigned)__bfloat16_as_ushort(h1) << 16);
    unsigned low = __bfloat16_as_ushort(l0) |
                   ((unsigned)__bfloat16_as_ushort(l1) << 16);
    *(unsigned*)(Ohi + base + lane * 2) = hiw;
    *(unsigned*)(Olo + base + lane * 2) = low;
}

// ---------------------------------------------------------------------------
// Launch
// ---------------------------------------------------------------------------
extern "C" void kernel_launch(void* const* d_in, const int* in_sizes, int n_in,
                              void* d_out, int out_size)
{
    const float* hs  = (const float*)d_in[0];
    const float* w_q = (const float*)d_in[1];
    const float* b_q = (const float*)d_in[2];
    const float* w_k = (const float*)d_in[3];
    const float* b_k = (const float*)d_in[4];
    const float* w_v = (const float*)d_in[5];
    const float* b_v = (const float*)d_in[6];
    const float* w_o = (const float*)d_in[7];
    const float* b_o = (const float*)d_in[8];
    float* out = (float*)d_out;

    float *qb, *kb, *vb;
    __nv_bfloat16 *ah, *al, *oh, *ol, *wh, *wl;
    cudaGetSymbolAddress((void**)&qb, g_q);
    cudaGetSymbolAddress((void**)&kb, g_k);
    cudaGetSymbolAddress((void**)&vb, g_v);
    cudaGetSymbolAddress((void**)&ah, g_a_hi);
    cudaGetSymbolAddress((void**)&al, g_a_lo);
    cudaGetSymbolAddress((void**)&oh, g_o_hi);
    cudaGetSymbolAddress((void**)&ol, g_o_lo);
    cudaGetSymbolAddress((void**)&wh, g_w_hi);
    cudaGetSymbolAddress((void**)&wl, g_w_lo);

    cudaFuncSetAttribute(gemm_mma, cudaFuncAttributeMaxDynamicSharedMemorySize,
                         SMEMB);

    const int act_blocks = (M_ROWS * HID) / (256 * 4);   // 16384

    // 1) decompose activations + weights
    decompose_act<<<act_blocks, 256>>>(hs, ah, al);
    decompose_w<<<dim3(32, 32, 4), 256>>>(w_q, w_k, w_v, w_o, wh, wl);

    // 2) fused QKV GEMM: 3 matrices x 4 N-tiles(256) x 128 M-tiles
    gemm_mma<<<dim3(12, 128), 512, SMEMB>>>(
        ah, al, wh, wl, 0, b_q, b_k, b_v, qb, kb, vb);

    // 3) neighborhood attention (emits bf16 hi/lo directly)
    neigh_attn_kernel<<<(BATCH * NHEADS * SEQ) / 8, 256>>>(qb, kb, vb, oh, ol);

    // 4) O projection
    gemm_mma<<<dim3(4, 128), 512, SMEMB>>>(
        oh, ol, wh, wl, 3, b_o, b_o, b_o, out, out, out);
}